// round 16
// baseline (speedup 1.0000x reference)
#include <cuda_runtime.h>
#include <cstdint>

// ---------------------------------------------------------------------------
// SPELL forward, algebraically collapsed:
//   per node:  a[4] = feat128 . Wa + x4 . Sa + Ta[spk_idx] + Ca   (face cols 0,1; body cols 2,3)
//              b[4] = feat128 . Wb + x4 . Sb + Tb[spk_idx] + Cb
//   per edge:  m[dst] = max(m[dst], b[src])          (4 channels, ordered-uint atomicMax)
//   output:    out[i] = hasEdge ? (a_f + m_f) + (a_b + m_b) : 0
// ---------------------------------------------------------------------------

#define MAXN   50176
#define D_IN   901
#define INITU  0x007fffffu   // f2u(-inf)
#define NODE_BLOCKS 1184     // 8 warps each

__device__ float  g_Wa[512];   // [col][k]  col = fam*2 + c, k<128  (col*128+k)
__device__ float  g_Wb[512];
__device__ float  g_Sa[16];    // col*4 + t
__device__ float  g_Sb[16];
__device__ float  g_Ta[12];    // col*3 + r
__device__ float  g_Tb[12];
__device__ float  g_Ca[4];
__device__ float  g_Cb[4];
__device__ float4 g_a[MAXN];
__device__ float4 g_b[MAXN];
__device__ uint4  g_m[MAXN];

__device__ __forceinline__ unsigned f2u(float f) {
    unsigned u = __float_as_uint(f);
    return (u & 0x80000000u) ? ~u : (u | 0x80000000u);
}
__device__ __forceinline__ float u2f(unsigned u) {
    unsigned v = (u & 0x80000000u) ? (u & 0x7fffffffu) : ~u;
    return __uint_as_float(v);
}

// ---------------------------------------------------------------------------
// Precompute composed weights (R15 smem-staged version). grid=2, 256 thr.
// ---------------------------------------------------------------------------
__global__ void __launch_bounds__(256, 1) precompute_kernel(
    const float* __restrict__ spkw, const float* __restrict__ spkb,
    const float* __restrict__ spaw, const float* __restrict__ spab,
    const float* __restrict__ f1w,  const float* __restrict__ f1b,
    const float* __restrict__ f2w,  const float* __restrict__ f2b,
    const float* __restrict__ few,  const float* __restrict__ feb,
    const float* __restrict__ g1w,  const float* __restrict__ g1b,
    const float* __restrict__ g2w,  const float* __restrict__ g2b,
    const float* __restrict__ gew,  const float* __restrict__ geb)
{
    int fam = blockIdx.x;
    int tid = threadIdx.x;
    const float* w1 = fam ? g1w : f1w;
    const float* b1 = fam ? g1b : f1b;
    const float* w2 = fam ? g2w : f2w;
    const float* b2 = fam ? g2b : f2b;
    const float* we = fam ? gew : few;
    const float* eb = fam ? geb : feb;

    __shared__ float s_w12[128 * 65];                  // (w1+w2)[k][j], pad 65
    __shared__ float s_w2x[32 * 65];                   // w2 rows 128..159, pad 65
    __shared__ float s_b12[64];                        // b1+b2
    __shared__ float s_wea[2][64], s_web[2][64];       // [c][j]
    __shared__ float s_Pa[2][2][16], s_Pb[2][2][16];   // [which][c][s] 0=spk 1=spa

    for (int i = tid; i < 128 * 64; i += 256) {
        int k = i >> 6, j = i & 63;
        s_w12[k * 65 + j] = w1[i] + w2[i];
    }
    for (int i = tid; i < 32 * 64; i += 256) {
        int s = i >> 6, j = i & 63;
        s_w2x[s * 65 + j] = w2[128 * 64 + i];
    }
    if (tid < 64) s_b12[tid] = b1[tid] + b2[tid];
    if (tid < 128) {
        int j = tid >> 1, c = tid & 1;
        float wb = we[(64 + j) * 2 + c];
        s_web[c][j] = wb;
        s_wea[c][j] = we[j * 2 + c] - wb;
    }
    __syncthreads();

    {   // main composed weight
        int k = tid >> 1, c = tid & 1;
        float sa = 0.f, sb = 0.f;
#pragma unroll 8
        for (int j = 0; j < 64; j++) {
            float wk = s_w12[k * 65 + j];
            sa += wk * s_wea[c][j];
            sb += wk * s_web[c][j];
        }
        int col = fam * 2 + c;
        g_Wa[col * 128 + k] = sa;
        g_Wb[col * 128 + k] = sb;
    }

    if (tid < 64) {   // P intermediates
        int which = tid & 1, c = (tid >> 1) & 1, s = tid >> 2;
        int row = which ? (16 + s) : s;
        float pa = 0.f, pb = 0.f;
#pragma unroll 8
        for (int j = 0; j < 64; j++) {
            float v = s_w2x[row * 65 + j];
            pa += v * s_wea[c][j];
            pb += v * s_web[c][j];
        }
        s_Pa[which][c][s] = pa;
        s_Pb[which][c][s] = pb;
    }
    __syncthreads();

    if (tid < 8) {    // spatial table
        int t = tid >> 1, c = tid & 1;
        float sA = 0.f, sB = 0.f;
        for (int s = 0; s < 16; s++) {
            float sw = spaw[t * 16 + s];
            sA += sw * s_Pa[1][c][s];
            sB += sw * s_Pb[1][c][s];
        }
        int col = fam * 2 + c;
        g_Sa[col * 4 + t] = sA;
        g_Sb[col * 4 + t] = sB;
    }
    if (tid >= 32 && tid < 38) {   // speaker table
        int t2 = tid - 32;
        int rr = t2 >> 1, c = t2 & 1;
        float sA = 0.f, sB = 0.f;
        for (int s = 0; s < 16; s++) {
            float sw = spkw[rr * 16 + s] + spkb[s];
            sA += sw * s_Pa[0][c][s];
            sB += sw * s_Pb[0][c][s];
        }
        int col = fam * 2 + c;
        g_Ta[col * 3 + rr] = sA;
        g_Tb[col * 3 + rr] = sB;
    }
    if (tid >= 64 && tid < 66) {   // constant terms
        int c = tid - 64;
        float cA = eb[c], cB = 0.f;
        for (int j = 0; j < 64; j++) {
            float bj = s_b12[j];
            cA += bj * s_wea[c][j];
            cB += bj * s_web[c][j];
        }
        for (int s = 0; s < 16; s++) {
            float sb = spab[s];
            cA += sb * s_Pa[1][c][s];
            cB += sb * s_Pb[1][c][s];
        }
        int col = fam * 2 + c;
        g_Ca[col] = cA;
        g_Cb[col] = cB;
    }
}

// ---------------------------------------------------------------------------
// Node kernel (R13): persistent warps, 2 nodes/iter, weights in registers.
// ---------------------------------------------------------------------------
__global__ void __launch_bounds__(256, 3) node_kernel(const float* __restrict__ x, int N)
{
    __shared__ float sW[1024];          // [0..511]=Wa, [512..1023]=Wb
    for (int i = threadIdx.x; i < 512; i += 256) {
        sW[i] = g_Wa[i];
        sW[512 + i] = g_Wb[i];
    }
    __syncthreads();

    int warp = threadIdx.x >> 5;
    int lane = threadIdx.x & 31;

    float w[8][4];
#pragma unroll
    for (int ch = 0; ch < 4; ch++)
#pragma unroll
        for (int j = 0; j < 4; j++) {
            w[ch][j]     = sW[ch * 128 + lane + 32 * j];
            w[4 + ch][j] = sW[512 + ch * 128 + lane + 32 * j];
        }

    int g = lane >> 2;
    int c = g & 3;
    bool isA = g < 4;
    const float* S = isA ? g_Sa : g_Sb;
    const float* T = isA ? g_Ta : g_Tb;
    float S0 = S[c * 4 + 0], S1 = S[c * 4 + 1], S2 = S[c * 4 + 2], S3 = S[c * 4 + 3];
    float T0 = T[c * 3 + 0], T1 = T[c * 3 + 1], T2 = T[c * 3 + 2];
    float Cc = (isA ? g_Ca : g_Cb)[c];
    int sub = lane & 3;

    int gwarp = blockIdx.x * 8 + warp;
    int stride2 = NODE_BLOCKS * 8 * 2;

    for (int base = gwarp * 2; base < N; base += stride2) {
        int n0 = base;
        int n1 = (base + 1 < N) ? base + 1 : base;
        const float* row0 = x + (size_t)n0 * D_IN;
        const float* row1 = x + (size_t)n1 * D_IN;

        float vf[2][4], vb[2][4], tailv[2];
#pragma unroll
        for (int j = 0; j < 4; j++) {
            vf[0][j] = __ldg(row0 + lane + 32 * j);
            vb[0][j] = __ldg(row0 + 128 + lane + 32 * j);
            vf[1][j] = __ldg(row1 + lane + 32 * j);
            vb[1][j] = __ldg(row1 + 128 + 32 * j + lane);
        }
        tailv[0] = (lane < 5) ? __ldg(row0 + 896 + lane) : 0.f;
        tailv[1] = (lane < 5) ? __ldg(row1 + 896 + lane) : 0.f;

#pragma unroll
        for (int p = 0; p < 2; p++) {
            float v[8];
#pragma unroll
            for (int ch = 0; ch < 8; ch++) v[ch] = 0.f;
#pragma unroll
            for (int j = 0; j < 4; j++) {
                float f = vf[p][j];
                float b = vb[p][j];
                v[0] += f * w[0][j];
                v[1] += f * w[1][j];
                v[2] += b * w[2][j];
                v[3] += b * w[3][j];
                v[4] += f * w[4][j];
                v[5] += f * w[5][j];
                v[6] += b * w[6][j];
                v[7] += b * w[7][j];
            }

#pragma unroll
            for (int i = 0; i < 4; i++) {
                float send = (lane & 16) ? v[i] : v[4 + i];
                float r = __shfl_xor_sync(0xffffffffu, send, 16);
                v[i] = ((lane & 16) ? v[4 + i] : v[i]) + r;
            }
#pragma unroll
            for (int i = 0; i < 2; i++) {
                float send = (lane & 8) ? v[i] : v[2 + i];
                float r = __shfl_xor_sync(0xffffffffu, send, 8);
                v[i] = ((lane & 8) ? v[2 + i] : v[i]) + r;
            }
            {
                float send = (lane & 4) ? v[0] : v[1];
                float r = __shfl_xor_sync(0xffffffffu, send, 4);
                v[0] = ((lane & 4) ? v[1] : v[0]) + r;
            }
            v[0] += __shfl_xor_sync(0xffffffffu, v[0], 2);
            v[0] += __shfl_xor_sync(0xffffffffu, v[0], 1);

            float t0  = __shfl_sync(0xffffffffu, tailv[p], 0);
            float t1  = __shfl_sync(0xffffffffu, tailv[p], 1);
            float t2  = __shfl_sync(0xffffffffu, tailv[p], 2);
            float t3  = __shfl_sync(0xffffffffu, tailv[p], 3);
            float cnt = __shfl_sync(0xffffffffu, tailv[p], 4);
            int idx = (int)cnt - 1;
            if (idx < 0) idx = 0;
            if (idx > 2) idx = 2;
            float Tv = (idx == 0) ? T0 : (idx == 1) ? T1 : T2;

            float val = v[0] + t0 * S0 + t1 * S1 + t2 * S2 + t3 * S3 + Tv + Cc;

            int node = (p == 0) ? n0 : n1;
            bool live = (p == 0) || (base + 1 < N);
            if (live) {
                if (sub == 0) {
                    float* dst = isA ? (float*)&g_a[node] : (float*)&g_b[node];
                    dst[c] = val;
                }
                if (sub == 1 && isA) {
                    ((unsigned*)&g_m[node])[c] = INITU;
                }
            }
        }
    }
}

// ---------------------------------------------------------------------------
// Edge kernel: 2 edges per thread (e and e+half) — both index loads stay
// coalesced, both b-gathers and peeks in flight before any atomic (MLP 2x).
// ---------------------------------------------------------------------------
__global__ void __launch_bounds__(256) edge_kernel(
    const int* __restrict__ ei, const int* __restrict__ ea, int E, int half)
{
    int t = blockIdx.x * blockDim.x + threadIdx.x;
    if (t >= half) {
        // tail thread: handles the odd last edge if E is odd
        if (t == half && (E & 1)) {
            int e = E - 1;
            int attr = ea[e];
            if (attr == 111 || attr == 0) {
                int src = ei[e];
                int dst = ei[E + e];
                float4 bv = g_b[src];
                uint4 cur = *(const uint4*)&g_m[dst];
                unsigned* m = (unsigned*)&g_m[dst];
                unsigned u0 = f2u(bv.x), u1 = f2u(bv.y), u2 = f2u(bv.z), u3 = f2u(bv.w);
                if (u0 > cur.x) atomicMax(m + 0, u0);
                if (u1 > cur.y) atomicMax(m + 1, u1);
                if (u2 > cur.z) atomicMax(m + 2, u2);
                if (u3 > cur.w) atomicMax(m + 3, u3);
            }
        }
        return;
    }
    int e0 = t;
    int e1 = t + half;

    // all index loads first (coalesced, independent)
    int attr0 = ea[e0];
    int attr1 = ea[e1];
    int src0 = ei[e0];
    int src1 = ei[e1];
    int dst0 = ei[E + e0];
    int dst1 = ei[E + e1];

    bool ok0 = (attr0 == 111) | (attr0 == 0);
    bool ok1 = (attr1 == 111) | (attr1 == 0);
    if (!ok0) src0 = src1;   // keep load uniform; result unused
    if (!ok1) src1 = src0;

    // both gathers in flight together
    float4 b0 = g_b[src0];
    float4 b1 = g_b[src1];
    // both peeks in flight together (monotone, non-atomic: safe)
    uint4 c0 = *(const uint4*)&g_m[dst0];
    uint4 c1 = *(const uint4*)&g_m[dst1];

    if (ok0) {
        unsigned* m = (unsigned*)&g_m[dst0];
        unsigned u0 = f2u(b0.x), u1 = f2u(b0.y), u2 = f2u(b0.z), u3 = f2u(b0.w);
        if (u0 > c0.x) atomicMax(m + 0, u0);
        if (u1 > c0.y) atomicMax(m + 1, u1);
        if (u2 > c0.z) atomicMax(m + 2, u2);
        if (u3 > c0.w) atomicMax(m + 3, u3);
    }
    if (ok1) {
        unsigned* m = (unsigned*)&g_m[dst1];
        unsigned u0 = f2u(b1.x), u1 = f2u(b1.y), u2 = f2u(b1.z), u3 = f2u(b1.w);
        if (u0 > c1.x) atomicMax(m + 0, u0);
        if (u1 > c1.y) atomicMax(m + 1, u1);
        if (u2 > c1.z) atomicMax(m + 2, u2);
        if (u3 > c1.w) atomicMax(m + 3, u3);
    }
}

// ---------------------------------------------------------------------------
// Output kernel: combine face+body; empty segments -> 0.
// ---------------------------------------------------------------------------
__global__ void __launch_bounds__(256) out_kernel(float* __restrict__ out, int N)
{
    int i = blockIdx.x * blockDim.x + threadIdx.x;
    if (i >= N) return;
    uint4 mu = g_m[i];
    float2 o;
    if (mu.x == INITU) {
        o.x = 0.f;
        o.y = 0.f;
    } else {
        float4 a = g_a[i];
        o.x = (a.x + u2f(mu.x)) + (a.z + u2f(mu.z));
        o.y = (a.y + u2f(mu.y)) + (a.w + u2f(mu.w));
    }
    ((float2*)out)[i] = o;
}

extern "C" void kernel_launch(void* const* d_in, const int* in_sizes, int n_in,
                              void* d_out, int out_size)
{
    const float* x    = (const float*)d_in[0];
    const int*   ei   = (const int*)d_in[1];
    const int*   ea   = (const int*)d_in[2];
    const float* spkw = (const float*)d_in[3];
    const float* spkb = (const float*)d_in[4];
    const float* spaw = (const float*)d_in[5];
    const float* spab = (const float*)d_in[6];
    const float* f1w  = (const float*)d_in[7];
    const float* f1b  = (const float*)d_in[8];
    const float* f2w  = (const float*)d_in[9];
    const float* f2b  = (const float*)d_in[10];
    const float* few  = (const float*)d_in[11];
    const float* feb  = (const float*)d_in[12];
    const float* g1w  = (const float*)d_in[13];
    const float* g1b  = (const float*)d_in[14];
    const float* g2w  = (const float*)d_in[15];
    const float* g2b  = (const float*)d_in[16];
    const float* gew  = (const float*)d_in[17];
    const float* geb  = (const float*)d_in[18];

    int N = in_sizes[0] / D_IN;
    int E = in_sizes[2];
    int half = E >> 1;

    precompute_kernel<<<2, 256>>>(spkw, spkb, spaw, spab,
                                  f1w, f1b, f2w, f2b, few, feb,
                                  g1w, g1b, g2w, g2b, gew, geb);
    node_kernel<<<NODE_BLOCKS, 256>>>(x, N);
    edge_kernel<<<(half + 256) / 256, 256>>>(ei, ea, E, half);
    out_kernel<<<(N + 255) / 256, 256>>>((float*)d_out, N);
}

// round 17
// speedup vs baseline: 1.1767x; 1.1767x over previous
#include <cuda_runtime.h>
#include <cstdint>

// ---------------------------------------------------------------------------
// SPELL forward, algebraically collapsed:
//   per node:  a[4] = feat128 . Wa + x4 . Sa + Ta[spk_idx] + Ca   (face cols 0,1; body cols 2,3)
//              b[4] = feat128 . Wb + x4 . Sb + Tb[spk_idx] + Cb
//   per edge:  m[dst] = max(m[dst], b[src])          (4 channels, ordered-uint atomicMax)
//   output:    out[i] = hasEdge ? (a_f + m_f) + (a_b + m_b) : 0
// ---------------------------------------------------------------------------

#define MAXN   50176
#define D_IN   901
#define INITU  0x007fffffu   // f2u(-inf)
#define NODE_BLOCKS 444      // 148 SMs x 3 resident blocks: ONE wave, persistent

__device__ float  g_Wa[512];   // [col][k]  col = fam*2 + c, k<128  (col*128+k)
__device__ float  g_Wb[512];
__device__ float  g_Sa[16];    // col*4 + t
__device__ float  g_Sb[16];
__device__ float  g_Ta[12];    // col*3 + r
__device__ float  g_Tb[12];
__device__ float  g_Ca[4];
__device__ float  g_Cb[4];
__device__ float4 g_a[MAXN];
__device__ float4 g_b[MAXN];
__device__ uint4  g_m[MAXN];

__device__ __forceinline__ unsigned f2u(float f) {
    unsigned u = __float_as_uint(f);
    return (u & 0x80000000u) ? ~u : (u | 0x80000000u);
}
__device__ __forceinline__ float u2f(unsigned u) {
    unsigned v = (u & 0x80000000u) ? (u & 0x7fffffffu) : ~u;
    return __uint_as_float(v);
}

// ---------------------------------------------------------------------------
// Precompute composed weights (R15 smem-staged version). grid=2, 256 thr.
// ---------------------------------------------------------------------------
__global__ void __launch_bounds__(256, 1) precompute_kernel(
    const float* __restrict__ spkw, const float* __restrict__ spkb,
    const float* __restrict__ spaw, const float* __restrict__ spab,
    const float* __restrict__ f1w,  const float* __restrict__ f1b,
    const float* __restrict__ f2w,  const float* __restrict__ f2b,
    const float* __restrict__ few,  const float* __restrict__ feb,
    const float* __restrict__ g1w,  const float* __restrict__ g1b,
    const float* __restrict__ g2w,  const float* __restrict__ g2b,
    const float* __restrict__ gew,  const float* __restrict__ geb)
{
    int fam = blockIdx.x;
    int tid = threadIdx.x;
    const float* w1 = fam ? g1w : f1w;
    const float* b1 = fam ? g1b : f1b;
    const float* w2 = fam ? g2w : f2w;
    const float* b2 = fam ? g2b : f2b;
    const float* we = fam ? gew : few;
    const float* eb = fam ? geb : feb;

    __shared__ float s_w12[128 * 65];                  // (w1+w2)[k][j], pad 65
    __shared__ float s_w2x[32 * 65];                   // w2 rows 128..159, pad 65
    __shared__ float s_b12[64];                        // b1+b2
    __shared__ float s_wea[2][64], s_web[2][64];       // [c][j]
    __shared__ float s_Pa[2][2][16], s_Pb[2][2][16];   // [which][c][s] 0=spk 1=spa

    for (int i = tid; i < 128 * 64; i += 256) {
        int k = i >> 6, j = i & 63;
        s_w12[k * 65 + j] = w1[i] + w2[i];
    }
    for (int i = tid; i < 32 * 64; i += 256) {
        int s = i >> 6, j = i & 63;
        s_w2x[s * 65 + j] = w2[128 * 64 + i];
    }
    if (tid < 64) s_b12[tid] = b1[tid] + b2[tid];
    if (tid < 128) {
        int j = tid >> 1, c = tid & 1;
        float wb = we[(64 + j) * 2 + c];
        s_web[c][j] = wb;
        s_wea[c][j] = we[j * 2 + c] - wb;
    }
    __syncthreads();

    {   // main composed weight
        int k = tid >> 1, c = tid & 1;
        float sa = 0.f, sb = 0.f;
#pragma unroll 8
        for (int j = 0; j < 64; j++) {
            float wk = s_w12[k * 65 + j];
            sa += wk * s_wea[c][j];
            sb += wk * s_web[c][j];
        }
        int col = fam * 2 + c;
        g_Wa[col * 128 + k] = sa;
        g_Wb[col * 128 + k] = sb;
    }

    if (tid < 64) {   // P intermediates
        int which = tid & 1, c = (tid >> 1) & 1, s = tid >> 2;
        int row = which ? (16 + s) : s;
        float pa = 0.f, pb = 0.f;
#pragma unroll 8
        for (int j = 0; j < 64; j++) {
            float v = s_w2x[row * 65 + j];
            pa += v * s_wea[c][j];
            pb += v * s_web[c][j];
        }
        s_Pa[which][c][s] = pa;
        s_Pb[which][c][s] = pb;
    }
    __syncthreads();

    if (tid < 8) {    // spatial table
        int t = tid >> 1, c = tid & 1;
        float sA = 0.f, sB = 0.f;
        for (int s = 0; s < 16; s++) {
            float sw = spaw[t * 16 + s];
            sA += sw * s_Pa[1][c][s];
            sB += sw * s_Pb[1][c][s];
        }
        int col = fam * 2 + c;
        g_Sa[col * 4 + t] = sA;
        g_Sb[col * 4 + t] = sB;
    }
    if (tid >= 32 && tid < 38) {   // speaker table
        int t2 = tid - 32;
        int rr = t2 >> 1, c = t2 & 1;
        float sA = 0.f, sB = 0.f;
        for (int s = 0; s < 16; s++) {
            float sw = spkw[rr * 16 + s] + spkb[s];
            sA += sw * s_Pa[0][c][s];
            sB += sw * s_Pb[0][c][s];
        }
        int col = fam * 2 + c;
        g_Ta[col * 3 + rr] = sA;
        g_Tb[col * 3 + rr] = sB;
    }
    if (tid >= 64 && tid < 66) {   // constant terms
        int c = tid - 64;
        float cA = eb[c], cB = 0.f;
        for (int j = 0; j < 64; j++) {
            float bj = s_b12[j];
            cA += bj * s_wea[c][j];
            cB += bj * s_web[c][j];
        }
        for (int s = 0; s < 16; s++) {
            float sb = spab[s];
            cA += sb * s_Pa[1][c][s];
            cB += sb * s_Pb[1][c][s];
        }
        int col = fam * 2 + c;
        g_Ca[col] = cA;
        g_Cb[col] = cB;
    }
}

// ---------------------------------------------------------------------------
// Node kernel: persistent warps (ONE wave of 444 blocks), 2 nodes/iter,
// weights + epilogue constants in registers; ~7 iterations per warp.
// ---------------------------------------------------------------------------
__global__ void __launch_bounds__(256, 3) node_kernel(const float* __restrict__ x, int N)
{
    __shared__ float sW[1024];          // [0..511]=Wa, [512..1023]=Wb
    for (int i = threadIdx.x; i < 512; i += 256) {
        sW[i] = g_Wa[i];
        sW[512 + i] = g_Wb[i];
    }
    __syncthreads();

    int warp = threadIdx.x >> 5;
    int lane = threadIdx.x & 31;

    float w[8][4];
#pragma unroll
    for (int ch = 0; ch < 4; ch++)
#pragma unroll
        for (int j = 0; j < 4; j++) {
            w[ch][j]     = sW[ch * 128 + lane + 32 * j];
            w[4 + ch][j] = sW[512 + ch * 128 + lane + 32 * j];
        }

    int g = lane >> 2;
    int c = g & 3;
    bool isA = g < 4;
    const float* S = isA ? g_Sa : g_Sb;
    const float* T = isA ? g_Ta : g_Tb;
    float S0 = S[c * 4 + 0], S1 = S[c * 4 + 1], S2 = S[c * 4 + 2], S3 = S[c * 4 + 3];
    float T0 = T[c * 3 + 0], T1 = T[c * 3 + 1], T2 = T[c * 3 + 2];
    float Cc = (isA ? g_Ca : g_Cb)[c];
    int sub = lane & 3;

    int gwarp = blockIdx.x * 8 + warp;
    int stride2 = NODE_BLOCKS * 8 * 2;

    for (int base = gwarp * 2; base < N; base += stride2) {
        int n0 = base;
        int n1 = (base + 1 < N) ? base + 1 : base;
        const float* row0 = x + (size_t)n0 * D_IN;
        const float* row1 = x + (size_t)n1 * D_IN;

        float vf[2][4], vb[2][4], tailv[2];
#pragma unroll
        for (int j = 0; j < 4; j++) {
            vf[0][j] = __ldg(row0 + lane + 32 * j);
            vb[0][j] = __ldg(row0 + 128 + lane + 32 * j);
            vf[1][j] = __ldg(row1 + lane + 32 * j);
            vb[1][j] = __ldg(row1 + 128 + 32 * j + lane);
        }
        tailv[0] = (lane < 5) ? __ldg(row0 + 896 + lane) : 0.f;
        tailv[1] = (lane < 5) ? __ldg(row1 + 896 + lane) : 0.f;

#pragma unroll
        for (int p = 0; p < 2; p++) {
            float v[8];
#pragma unroll
            for (int ch = 0; ch < 8; ch++) v[ch] = 0.f;
#pragma unroll
            for (int j = 0; j < 4; j++) {
                float f = vf[p][j];
                float b = vb[p][j];
                v[0] += f * w[0][j];
                v[1] += f * w[1][j];
                v[2] += b * w[2][j];
                v[3] += b * w[3][j];
                v[4] += f * w[4][j];
                v[5] += f * w[5][j];
                v[6] += b * w[6][j];
                v[7] += b * w[7][j];
            }

#pragma unroll
            for (int i = 0; i < 4; i++) {
                float send = (lane & 16) ? v[i] : v[4 + i];
                float r = __shfl_xor_sync(0xffffffffu, send, 16);
                v[i] = ((lane & 16) ? v[4 + i] : v[i]) + r;
            }
#pragma unroll
            for (int i = 0; i < 2; i++) {
                float send = (lane & 8) ? v[i] : v[2 + i];
                float r = __shfl_xor_sync(0xffffffffu, send, 8);
                v[i] = ((lane & 8) ? v[2 + i] : v[i]) + r;
            }
            {
                float send = (lane & 4) ? v[0] : v[1];
                float r = __shfl_xor_sync(0xffffffffu, send, 4);
                v[0] = ((lane & 4) ? v[1] : v[0]) + r;
            }
            v[0] += __shfl_xor_sync(0xffffffffu, v[0], 2);
            v[0] += __shfl_xor_sync(0xffffffffu, v[0], 1);

            float t0  = __shfl_sync(0xffffffffu, tailv[p], 0);
            float t1  = __shfl_sync(0xffffffffu, tailv[p], 1);
            float t2  = __shfl_sync(0xffffffffu, tailv[p], 2);
            float t3  = __shfl_sync(0xffffffffu, tailv[p], 3);
            float cnt = __shfl_sync(0xffffffffu, tailv[p], 4);
            int idx = (int)cnt - 1;
            if (idx < 0) idx = 0;
            if (idx > 2) idx = 2;
            float Tv = (idx == 0) ? T0 : (idx == 1) ? T1 : T2;

            float val = v[0] + t0 * S0 + t1 * S1 + t2 * S2 + t3 * S3 + Tv + Cc;

            int node = (p == 0) ? n0 : n1;
            bool live = (p == 0) || (base + 1 < N);
            if (live) {
                if (sub == 0) {
                    float* dst = isA ? (float*)&g_a[node] : (float*)&g_b[node];
                    dst[c] = val;
                }
                if (sub == 1 && isA) {
                    ((unsigned*)&g_m[node])[c] = INITU;
                }
            }
        }
    }
}

// ---------------------------------------------------------------------------
// Edge kernel (R15 proven form): 1 edge/thread; gather b[src]; monotone peek;
// RED.MAX. 87% occupancy supplies cross-warp MLP through L2.
// ---------------------------------------------------------------------------
__global__ void __launch_bounds__(256) edge_kernel(
    const int* __restrict__ ei, const int* __restrict__ ea, int E)
{
    int e = blockIdx.x * blockDim.x + threadIdx.x;
    if (e >= E) return;
    int attr = ea[e];
    if (attr != 111 && attr != 0) return;
    int src = ei[e];
    int dst = ei[E + e];
    float4 bv = g_b[src];
    unsigned u0 = f2u(bv.x), u1 = f2u(bv.y), u2 = f2u(bv.z), u3 = f2u(bv.w);
    uint4 cur = *(const uint4*)&g_m[dst];   // non-atomic peek (monotone, safe)
    unsigned* m = (unsigned*)&g_m[dst];
    if (u0 > cur.x) atomicMax(m + 0, u0);
    if (u1 > cur.y) atomicMax(m + 1, u1);
    if (u2 > cur.z) atomicMax(m + 2, u2);
    if (u3 > cur.w) atomicMax(m + 3, u3);
}

// ---------------------------------------------------------------------------
// Output kernel: combine face+body; empty segments -> 0.
// ---------------------------------------------------------------------------
__global__ void __launch_bounds__(256) out_kernel(float* __restrict__ out, int N)
{
    int i = blockIdx.x * blockDim.x + threadIdx.x;
    if (i >= N) return;
    uint4 mu = g_m[i];
    float2 o;
    if (mu.x == INITU) {
        o.x = 0.f;
        o.y = 0.f;
    } else {
        float4 a = g_a[i];
        o.x = (a.x + u2f(mu.x)) + (a.z + u2f(mu.z));
        o.y = (a.y + u2f(mu.y)) + (a.w + u2f(mu.w));
    }
    ((float2*)out)[i] = o;
}

extern "C" void kernel_launch(void* const* d_in, const int* in_sizes, int n_in,
                              void* d_out, int out_size)
{
    const float* x    = (const float*)d_in[0];
    const int*   ei   = (const int*)d_in[1];
    const int*   ea   = (const int*)d_in[2];
    const float* spkw = (const float*)d_in[3];
    const float* spkb = (const float*)d_in[4];
    const float* spaw = (const float*)d_in[5];
    const float* spab = (const float*)d_in[6];
    const float* f1w  = (const float*)d_in[7];
    const float* f1b  = (const float*)d_in[8];
    const float* f2w  = (const float*)d_in[9];
    const float* f2b  = (const float*)d_in[10];
    const float* few  = (const float*)d_in[11];
    const float* feb  = (const float*)d_in[12];
    const float* g1w  = (const float*)d_in[13];
    const float* g1b  = (const float*)d_in[14];
    const float* g2w  = (const float*)d_in[15];
    const float* g2b  = (const float*)d_in[16];
    const float* gew  = (const float*)d_in[17];
    const float* geb  = (const float*)d_in[18];

    int N = in_sizes[0] / D_IN;
    int E = in_sizes[2];

    precompute_kernel<<<2, 256>>>(spkw, spkb, spaw, spab,
                                  f1w, f1b, f2w, f2b, few, feb,
                                  g1w, g1b, g2w, g2b, gew, geb);
    node_kernel<<<NODE_BLOCKS, 256>>>(x, N);
    edge_kernel<<<(E + 255) / 256, 256>>>(ei, ea, E);
    out_kernel<<<(N + 255) / 256, 256>>>((float*)d_out, N);
}